// round 3
// baseline (speedup 1.0000x reference)
#include <cuda_runtime.h>

#define NN 20000
#define EE 320000
#define ET (EE + NN)
#define BB 128

// ---------------- scratch (device globals; no runtime allocation) ----------
__device__ int   g_flag;
__device__ int   g_src[EE], g_dst[EE], g_batch[NN];
__device__ int   g_deg[NN], g_cur[NN], g_off[NN + 1];
__device__ int   g_csr[ET];
__device__ float g_h0[NN * 64];
__device__ float g_xh[(size_t)NN * 512];
__device__ float g_as[NN * 8], g_ad[NN * 8];
__device__ float g_agg[(size_t)NN * 512];
__device__ float g_outf[NN * 64];
__device__ float g_e2[NN];
__device__ float g_hs[BB * 64], g_cs[BB * 64], g_qstar[BB * 128];
__device__ int   g_seg[BB + 1];

// ---------------- dtype detection (int64 vs int32 index buffers) -----------
__global__ void k_detect(const int* buf) {
    int t = threadIdx.x;
    int any = 0;
    for (int i = 2 * t + 1; i < 2048; i += 2 * 256) any |= (buf[i] != 0);
    __shared__ int s;
    if (t == 0) s = 0;
    __syncthreads();
    if (any) atomicOr(&s, 1);
    __syncthreads();
    if (t == 0) g_flag = s ? 0 : 1;  // 1 => int64
}

__global__ void k_convert(const void* edge, const void* batch, int E, int n) {
    int is64 = g_flag;
    for (int i = blockIdx.x * blockDim.x + threadIdx.x; i < E;
         i += gridDim.x * blockDim.x) {
        if (is64) {
            const long long* p = (const long long*)edge;
            g_src[i] = (int)p[i];
            g_dst[i] = (int)p[(size_t)E + i];
        } else {
            const int* p = (const int*)edge;
            g_src[i] = p[i];
            g_dst[i] = p[E + i];
        }
        if (i < n) {
            g_batch[i] = is64 ? (int)((const long long*)batch)[i]
                              : ((const int*)batch)[i];
        }
    }
}

// ---------------- zero-init per launch --------------------------------------
__global__ void k_init(int n) {
    int tot = 2 * n + BB * 128 + 2 * BB * 64;
    for (int i = blockIdx.x * blockDim.x + threadIdx.x; i < tot;
         i += gridDim.x * blockDim.x) {
        if (i < n) g_deg[i] = 0;
        else if (i < 2 * n) g_cur[i - n] = 0;
        else {
            int j = i - 2 * n;
            if (j < BB * 128) g_qstar[j] = 0.f;
            else {
                j -= BB * 128;
                if (j < BB * 64) g_hs[j] = 0.f;
                else g_cs[j - BB * 64] = 0.f;
            }
        }
    }
}

// ---------------- h0 = relu(x @ W0 + b0) ------------------------------------
__global__ void k_h0(const float* __restrict__ x, const float* __restrict__ W0,
                     const float* __restrict__ b0, int n) {
    __shared__ float Ws[25 * 64];
    __shared__ float xs[4][25];
    int t = threadIdx.x;  // 256
    for (int idx = t; idx < 25 * 64; idx += 256) Ws[idx] = W0[idx];
    int n0 = blockIdx.x * 4;
    if (t < 100) {
        int g = t / 25, k = t % 25;
        int gn = n0 + g;
        xs[g][k] = (gn < n) ? x[gn * 25 + k] : 0.f;
    }
    __syncthreads();
    int g = t >> 6, j = t & 63;
    int gn = n0 + g;
    if (gn < n) {
        float acc = b0[j];
#pragma unroll
        for (int k = 0; k < 25; k++) acc += xs[g][k] * Ws[k * 64 + j];
        g_h0[gn * 64 + j] = fmaxf(acc, 0.f);
    }
}

// ---------------- GEMM1: xh = h0 @ Wg ; fused a_s, a_d ----------------------
// grid (ceil(n/64), 8 heads), 256 threads, each thread 4x4 outputs
__global__ void k_gemm1(const float* __restrict__ Wg,
                        const float* __restrict__ att_src,
                        const float* __restrict__ att_dst, int n) {
    __shared__ float As[64][65];  // As[k][r]
    __shared__ float Bs[64][65];  // Bs[k][c]
    __shared__ float attS[64], attD[64];
    __shared__ float redS[16][64], redD[16][64];
    int h = blockIdx.y;
    int row0 = blockIdx.x * 64;
    int t = threadIdx.x;
    int tx = t & 15, ty = t >> 4;
    for (int idx = t; idx < 4096; idx += 256) {
        int r = idx >> 6, k = idx & 63;
        int gr = row0 + r;
        As[k][r] = (gr < n) ? g_h0[gr * 64 + k] : 0.f;
    }
    for (int idx = t; idx < 4096; idx += 256) {
        int k = idx >> 6, c = idx & 63;
        Bs[k][c] = Wg[k * 512 + h * 64 + c];
    }
    if (t < 64) {
        attS[t] = att_src[h * 64 + t];
        attD[t] = att_dst[h * 64 + t];
    }
    __syncthreads();
    float acc[4][4];
#pragma unroll
    for (int i = 0; i < 4; i++)
#pragma unroll
        for (int j = 0; j < 4; j++) acc[i][j] = 0.f;
#pragma unroll 8
    for (int k = 0; k < 64; k++) {
        float a0 = As[k][ty * 4 + 0], a1 = As[k][ty * 4 + 1];
        float a2 = As[k][ty * 4 + 2], a3 = As[k][ty * 4 + 3];
        float b0 = Bs[k][tx * 4 + 0], b1 = Bs[k][tx * 4 + 1];
        float b2 = Bs[k][tx * 4 + 2], b3 = Bs[k][tx * 4 + 3];
        acc[0][0] += a0 * b0; acc[0][1] += a0 * b1; acc[0][2] += a0 * b2; acc[0][3] += a0 * b3;
        acc[1][0] += a1 * b0; acc[1][1] += a1 * b1; acc[1][2] += a1 * b2; acc[1][3] += a1 * b3;
        acc[2][0] += a2 * b0; acc[2][1] += a2 * b1; acc[2][2] += a2 * b2; acc[2][3] += a2 * b3;
        acc[3][0] += a3 * b0; acc[3][1] += a3 * b1; acc[3][2] += a3 * b2; acc[3][3] += a3 * b3;
    }
    float ats0 = attS[tx * 4 + 0], ats1 = attS[tx * 4 + 1];
    float ats2 = attS[tx * 4 + 2], ats3 = attS[tx * 4 + 3];
    float atd0 = attD[tx * 4 + 0], atd1 = attD[tx * 4 + 1];
    float atd2 = attD[tx * 4 + 2], atd3 = attD[tx * 4 + 3];
#pragma unroll
    for (int i = 0; i < 4; i++) {
        int gr = row0 + ty * 4 + i;
        if (gr < n) {
            float4 v = make_float4(acc[i][0], acc[i][1], acc[i][2], acc[i][3]);
            *(float4*)(g_xh + (size_t)gr * 512 + h * 64 + tx * 4) = v;
        }
        float ps = acc[i][0] * ats0 + acc[i][1] * ats1 + acc[i][2] * ats2 + acc[i][3] * ats3;
        float pd = acc[i][0] * atd0 + acc[i][1] * atd1 + acc[i][2] * atd2 + acc[i][3] * atd3;
        redS[tx][ty * 4 + i] = ps;
        redD[tx][ty * 4 + i] = pd;
    }
    __syncthreads();
    if (t < 64) {
        float s = 0.f, d = 0.f;
#pragma unroll
        for (int xw = 0; xw < 16; xw++) { s += redS[xw][t]; d += redD[xw][t]; }
        int gr = row0 + t;
        if (gr < n) {
            g_as[gr * 8 + h] = s;
            g_ad[gr * 8 + h] = d;
        }
    }
}

// ---------------- CSR build --------------------------------------------------
__global__ void k_count(int E, int n) {
    int tot = E + n;
    for (int i = blockIdx.x * blockDim.x + threadIdx.x; i < tot;
         i += gridDim.x * blockDim.x) {
        int d = (i < E) ? g_dst[i] : (i - E);  // self-loops appended
        atomicAdd(&g_deg[d], 1);
    }
}

__global__ void k_scan(int n) {
    __shared__ int sd[1024];
    __shared__ int carry;
    int t = threadIdx.x;
    if (t == 0) carry = 0;
    __syncthreads();
    for (int base = 0; base < n; base += 1024) {
        int v = (base + t < n) ? g_deg[base + t] : 0;
        sd[t] = v;
        __syncthreads();
        for (int o = 1; o < 1024; o <<= 1) {
            int xv = (t >= o) ? sd[t - o] : 0;
            __syncthreads();
            sd[t] += xv;
            __syncthreads();
        }
        int cprev = carry;
        if (base + t < n) g_off[base + t] = cprev + sd[t] - v;
        __syncthreads();
        if (t == 0) carry = cprev + sd[1023];
        __syncthreads();
    }
    if (t == 0) g_off[n] = carry;
}

__global__ void k_scatter(int E, int n) {
    int tot = E + n;
    for (int i = blockIdx.x * blockDim.x + threadIdx.x; i < tot;
         i += gridDim.x * blockDim.x) {
        int d = (i < E) ? g_dst[i] : (i - E);
        int s = (i < E) ? g_src[i] : (i - E);
        int pos = g_off[d] + atomicAdd(&g_cur[d], 1);
        g_csr[pos] = s;
    }
}

// ---------------- per-dst softmax + aggregate + bias + relu -----------------
__global__ void k_agg(const float* __restrict__ bg) {
    int dst = blockIdx.x;
    int t = threadIdx.x;  // 128
    int lane = t & 31, wrp = t >> 5;
    __shared__ float s_m[8], s_inv[8];
    __shared__ float scratch[32];
    __shared__ int   s_srcb[128];
    __shared__ float s_al[128 * 8];
    int start = g_off[dst], end = g_off[dst + 1];
    float ad[8];
#pragma unroll
    for (int h = 0; h < 8; h++) ad[h] = g_ad[dst * 8 + h];

    // pass 1: max per head
    float lm[8];
#pragma unroll
    for (int h = 0; h < 8; h++) lm[h] = -1e30f;
    for (int jj = start + t; jj < end; jj += 128) {
        int s = g_csr[jj];
        const float* ap = g_as + s * 8;
#pragma unroll
        for (int h = 0; h < 8; h++) {
            float e = ap[h] + ad[h];
            e = (e > 0.f) ? e : 0.2f * e;
            lm[h] = fmaxf(lm[h], e);
        }
    }
#pragma unroll
    for (int h = 0; h < 8; h++)
        for (int o = 16; o; o >>= 1)
            lm[h] = fmaxf(lm[h], __shfl_xor_sync(0xffffffffu, lm[h], o));
    if (lane == 0)
#pragma unroll
        for (int h = 0; h < 8; h++) scratch[wrp * 8 + h] = lm[h];
    __syncthreads();
    if (t < 8)
        s_m[t] = fmaxf(fmaxf(scratch[t], scratch[8 + t]),
                       fmaxf(scratch[16 + t], scratch[24 + t]));
    __syncthreads();
    float mh[8];
#pragma unroll
    for (int h = 0; h < 8; h++) mh[h] = s_m[h];

    // pass 2: sum of exp
    float ls[8];
#pragma unroll
    for (int h = 0; h < 8; h++) ls[h] = 0.f;
    for (int jj = start + t; jj < end; jj += 128) {
        int s = g_csr[jj];
        const float* ap = g_as + s * 8;
#pragma unroll
        for (int h = 0; h < 8; h++) {
            float e = ap[h] + ad[h];
            e = (e > 0.f) ? e : 0.2f * e;
            ls[h] += __expf(e - mh[h]);
        }
    }
#pragma unroll
    for (int h = 0; h < 8; h++)
        for (int o = 16; o; o >>= 1)
            ls[h] += __shfl_xor_sync(0xffffffffu, ls[h], o);
    if (lane == 0)
#pragma unroll
        for (int h = 0; h < 8; h++) scratch[wrp * 8 + h] = ls[h];
    __syncthreads();
    if (t < 8) {
        float sm = scratch[t] + scratch[8 + t] + scratch[16 + t] + scratch[24 + t];
        s_inv[t] = 1.f / sm;
    }
    __syncthreads();
    float inv[8];
#pragma unroll
    for (int h = 0; h < 8; h++) inv[h] = s_inv[h];

    // pass 3: weighted gather, chunked
    int ht = t >> 4;  // head of this thread's 4 channels
    float4 acc = make_float4(0.f, 0.f, 0.f, 0.f);
    for (int base = start; base < end; base += 128) {
        int cnt = min(128, end - base);
        __syncthreads();
        if (t < cnt) {
            int s = g_csr[base + t];
            s_srcb[t] = s;
            const float* ap = g_as + s * 8;
#pragma unroll
            for (int h = 0; h < 8; h++) {
                float e = ap[h] + ad[h];
                e = (e > 0.f) ? e : 0.2f * e;
                s_al[t * 8 + h] = __expf(e - mh[h]) * inv[h];
            }
        }
        __syncthreads();
#pragma unroll 4
        for (int j = 0; j < cnt; j++) {
            float al = s_al[j * 8 + ht];
            const float4 v =
                *(const float4*)(g_xh + (size_t)s_srcb[j] * 512 + t * 4);
            acc.x += al * v.x;
            acc.y += al * v.y;
            acc.z += al * v.z;
            acc.w += al * v.w;
        }
    }
    float4 bgv = *(const float4*)(bg + t * 4);
    float4 o;
    o.x = fmaxf(acc.x + bgv.x, 0.f);
    o.y = fmaxf(acc.y + bgv.y, 0.f);
    o.z = fmaxf(acc.z + bgv.z, 0.f);
    o.w = fmaxf(acc.w + bgv.w, 0.f);
    *(float4*)(g_agg + (size_t)dst * 512 + t * 4) = o;
}

// ---------------- GEMM2: out = relu(agg @ Wh + bh) --------------------------
__global__ void k_gemm2(const float* __restrict__ Wh,
                        const float* __restrict__ bh, int n) {
    __shared__ float As[64][65];
    __shared__ float Bs[64][65];
    int row0 = blockIdx.x * 64;
    int t = threadIdx.x;
    int tx = t & 15, ty = t >> 4;
    float acc[4][4];
#pragma unroll
    for (int i = 0; i < 4; i++)
#pragma unroll
        for (int j = 0; j < 4; j++) acc[i][j] = 0.f;
    for (int k0 = 0; k0 < 512; k0 += 64) {
        __syncthreads();
        for (int idx = t; idx < 4096; idx += 256) {
            int r = idx >> 6, k = idx & 63;
            int gr = row0 + r;
            As[k][r] = (gr < n) ? g_agg[(size_t)gr * 512 + k0 + k] : 0.f;
        }
        for (int idx = t; idx < 4096; idx += 256) {
            int k = idx >> 6, c = idx & 63;
            Bs[k][c] = Wh[(k0 + k) * 64 + c];
        }
        __syncthreads();
#pragma unroll 8
        for (int k = 0; k < 64; k++) {
            float a0 = As[k][ty * 4 + 0], a1 = As[k][ty * 4 + 1];
            float a2 = As[k][ty * 4 + 2], a3 = As[k][ty * 4 + 3];
            float b0 = Bs[k][tx * 4 + 0], b1 = Bs[k][tx * 4 + 1];
            float b2 = Bs[k][tx * 4 + 2], b3 = Bs[k][tx * 4 + 3];
            acc[0][0] += a0 * b0; acc[0][1] += a0 * b1; acc[0][2] += a0 * b2; acc[0][3] += a0 * b3;
            acc[1][0] += a1 * b0; acc[1][1] += a1 * b1; acc[1][2] += a1 * b2; acc[1][3] += a1 * b3;
            acc[2][0] += a2 * b0; acc[2][1] += a2 * b1; acc[2][2] += a2 * b2; acc[2][3] += a2 * b3;
            acc[3][0] += a3 * b0; acc[3][1] += a3 * b1; acc[3][2] += a3 * b2; acc[3][3] += a3 * b3;
        }
    }
    float bh0 = bh[tx * 4 + 0], bh1 = bh[tx * 4 + 1];
    float bh2 = bh[tx * 4 + 2], bh3 = bh[tx * 4 + 3];
#pragma unroll
    for (int i = 0; i < 4; i++) {
        int gr = row0 + ty * 4 + i;
        if (gr < n) {
            float4 v;
            v.x = fmaxf(acc[i][0] + bh0, 0.f);
            v.y = fmaxf(acc[i][1] + bh1, 0.f);
            v.z = fmaxf(acc[i][2] + bh2, 0.f);
            v.w = fmaxf(acc[i][3] + bh3, 0.f);
            *(float4*)(g_outf + gr * 64 + tx * 4) = v;
        }
    }
}

// ---------------- segment boundaries for sorted batch -----------------------
__global__ void k_segstart(int n) {
    int b = threadIdx.x;
    if (b > BB) return;
    if (b == BB) { g_seg[BB] = n; return; }
    int lo = 0, hi = n;
    while (lo < hi) {
        int mid = (lo + hi) >> 1;
        if (g_batch[mid] < b) lo = mid + 1;
        else hi = mid;
    }
    g_seg[b] = lo;
}

// ---------------- LSTM cell (Set2Set) ---------------------------------------
__global__ void k_lstm(const float* __restrict__ W_ih,
                       const float* __restrict__ W_hh,
                       const float* __restrict__ b_ih,
                       const float* __restrict__ b_hh) {
    int b = blockIdx.x, j = threadIdx.x;  // 256 threads
    __shared__ float sq[128], sh[64], gg[256];
    if (j < 128) sq[j] = g_qstar[b * 128 + j];
    if (j < 64) sh[j] = g_hs[b * 64 + j];
    __syncthreads();
    float acc = b_ih[j] + b_hh[j];
    const float* wr = W_ih + j * 128;
#pragma unroll 8
    for (int k = 0; k < 128; k++) acc += sq[k] * wr[k];
    const float* wr2 = W_hh + j * 64;
#pragma unroll 8
    for (int k = 0; k < 64; k++) acc += sh[k] * wr2[k];
    gg[j] = acc;
    __syncthreads();
    if (j < 64) {
        float ig = 1.f / (1.f + __expf(-gg[j]));
        float fg = 1.f / (1.f + __expf(-gg[64 + j]));
        float gv = tanhf(gg[128 + j]);
        float og = 1.f / (1.f + __expf(-gg[192 + j]));
        float cn = fg * g_cs[b * 64 + j] + ig * gv;
        float hn = og * tanhf(cn);
        g_cs[b * 64 + j] = cn;
        g_hs[b * 64 + j] = hn;
    }
}

// ---------------- attention pooling (Set2Set) -------------------------------
__device__ __forceinline__ float blkmax128(float v, float* sb) {
    for (int o = 16; o; o >>= 1) v = fmaxf(v, __shfl_xor_sync(0xffffffffu, v, o));
    if ((threadIdx.x & 31) == 0) sb[threadIdx.x >> 5] = v;
    __syncthreads();
    v = fmaxf(fmaxf(sb[0], sb[1]), fmaxf(sb[2], sb[3]));
    __syncthreads();
    return v;
}
__device__ __forceinline__ float blksum128(float v, float* sb) {
    for (int o = 16; o; o >>= 1) v += __shfl_xor_sync(0xffffffffu, v, o);
    if ((threadIdx.x & 31) == 0) sb[threadIdx.x >> 5] = v;
    __syncthreads();
    v = sb[0] + sb[1] + sb[2] + sb[3];
    __syncthreads();
    return v;
}

__global__ void k_pool() {
    int b = blockIdx.x, t = threadIdx.x;  // 128
    __shared__ float q[64];
    __shared__ float sb[4];
    int s0 = g_seg[b], s1 = g_seg[b + 1];
    if (t < 64) q[t] = g_hs[b * 64 + t];
    __syncthreads();
    float mx = -1e30f;
    for (int i = s0 + t; i < s1; i += 128) {
        const float* row = g_outf + i * 64;
        float d = 0.f;
#pragma unroll
        for (int c = 0; c < 64; c += 4) {
            float4 v = *(const float4*)(row + c);
            d += v.x * q[c] + v.y * q[c + 1] + v.z * q[c + 2] + v.w * q[c + 3];
        }
        g_e2[i] = d;
        mx = fmaxf(mx, d);
    }
    mx = blkmax128(mx, sb);
    float sm = 0.f;
    for (int i = s0 + t; i < s1; i += 128) {
        float w = __expf(g_e2[i] - mx);
        g_e2[i] = w;
        sm += w;
    }
    sm = blksum128(sm, sb);
    float inv = (sm > 0.f) ? 1.f / sm : 0.f;
    if (t < 64) {
        float r = 0.f;
        for (int i = s0; i < s1; i++) r += g_e2[i] * g_outf[i * 64 + t];
        g_qstar[b * 128 + t] = q[t];
        g_qstar[b * 128 + 64 + t] = r * inv;
    }
}

// ---------------- final MLP: y = relu(q_star@W1+b1)@W2 + b2 -----------------
__global__ void k_final(const float* __restrict__ W1, const float* __restrict__ b1,
                        const float* __restrict__ W2, const float* __restrict__ b2,
                        float* __restrict__ y) {
    int b = blockIdx.x, j = threadIdx.x;  // 64 threads
    __shared__ float sq[128];
    __shared__ float sb[2];
    sq[j] = g_qstar[b * 128 + j];
    sq[64 + j] = g_qstar[b * 128 + 64 + j];
    __syncthreads();
    float acc = b1[j];
#pragma unroll 8
    for (int k = 0; k < 128; k++) acc += sq[k] * W1[k * 64 + j];
    float z = fmaxf(acc, 0.f) * W2[j];
    for (int o = 16; o; o >>= 1) z += __shfl_xor_sync(0xffffffffu, z, o);
    if ((j & 31) == 0) sb[j >> 5] = z;
    __syncthreads();
    if (j == 0) y[b] = sb[0] + sb[1] + b2[0];
}

// ---------------- launcher ---------------------------------------------------
extern "C" void kernel_launch(void* const* d_in, const int* in_sizes, int n_in,
                              void* d_out, int out_size) {
    const float* x      = (const float*)d_in[0];
    const void*  edge   = d_in[1];
    const void*  batch  = d_in[2];
    const float* W0     = (const float*)d_in[3];
    const float* b0     = (const float*)d_in[4];
    const float* Wg     = (const float*)d_in[5];
    const float* att_s  = (const float*)d_in[6];
    const float* att_d  = (const float*)d_in[7];
    const float* bg     = (const float*)d_in[8];
    const float* Wh     = (const float*)d_in[9];
    const float* bh     = (const float*)d_in[10];
    const float* W_ih   = (const float*)d_in[11];
    const float* W_hh   = (const float*)d_in[12];
    const float* b_ih   = (const float*)d_in[13];
    const float* b_hh   = (const float*)d_in[14];
    const float* W1     = (const float*)d_in[15];
    const float* b1     = (const float*)d_in[16];
    const float* W2     = (const float*)d_in[17];
    const float* b2     = (const float*)d_in[18];
    float* y = (float*)d_out;

    int n = in_sizes[0] / 25;
    int E = in_sizes[1] / 2;

    k_detect<<<1, 256>>>((const int*)edge);
    k_convert<<<512, 256>>>(edge, batch, E, n);
    k_init<<<256, 256>>>(n);
    k_h0<<<(n + 3) / 4, 256>>>(x, W0, b0, n);
    k_gemm1<<<dim3((n + 63) / 64, 8), 256>>>(Wg, att_s, att_d, n);
    k_count<<<1024, 256>>>(E, n);
    k_scan<<<1, 1024>>>(n);
    k_scatter<<<1024, 256>>>(E, n);
    k_agg<<<n, 128>>>(bg);
    k_gemm2<<<(n + 63) / 64, 256>>>(Wh, bh, n);
    k_segstart<<<1, 256>>>(n);
    for (int it = 0; it < 3; it++) {
        k_lstm<<<BB, 256>>>(W_ih, W_hh, b_ih, b_hh);
        k_pool<<<BB, 128>>>();
    }
    k_final<<<BB, 64>>>(W1, b1, W2, b2, y);
}

// round 4
// speedup vs baseline: 1.0257x; 1.0257x over previous
#include <cuda_runtime.h>

#define NN 20000
#define EE 320000
#define ET (EE + NN)
#define BB 128

// ---------------- scratch (device globals; no runtime allocation) ----------
__device__ int   g_flag;
__device__ int   g_src[EE], g_dst[EE], g_batch[NN];
__device__ int   g_deg[NN], g_cur[NN], g_off[NN + 1];
__device__ int   g_csr[ET];
__device__ float g_h0[NN * 64];
__device__ float g_pre[(size_t)NN * 512];      // aggpre [N][h*64+k]
__device__ float g_as[NN * 8], g_ad[NN * 8];
__device__ float g_Vs[64 * 8], g_Vd[64 * 8];
__device__ float g_outf[NN * 64];
__device__ float g_e2[NN];
__device__ float g_hs[BB * 64], g_cs[BB * 64], g_qstar[BB * 128];
__device__ int   g_seg[BB + 1];

// ---------------- dtype detection (int64 vs int32 index buffers) -----------
__global__ void k_detect(const int* buf) {
    int t = threadIdx.x;
    int any = 0;
    for (int i = 2 * t + 1; i < 2048; i += 2 * 256) any |= (buf[i] != 0);
    __shared__ int s;
    if (t == 0) s = 0;
    __syncthreads();
    if (any) atomicOr(&s, 1);
    __syncthreads();
    if (t == 0) g_flag = s ? 0 : 1;  // 1 => int64
}

__global__ void k_convert(const void* edge, const void* batch, int E, int n) {
    int is64 = g_flag;
    for (int i = blockIdx.x * blockDim.x + threadIdx.x; i < E;
         i += gridDim.x * blockDim.x) {
        if (is64) {
            const long long* p = (const long long*)edge;
            g_src[i] = (int)p[i];
            g_dst[i] = (int)p[(size_t)E + i];
        } else {
            const int* p = (const int*)edge;
            g_src[i] = p[i];
            g_dst[i] = p[E + i];
        }
        if (i < n) {
            g_batch[i] = is64 ? (int)((const long long*)batch)[i]
                              : ((const int*)batch)[i];
        }
    }
}

// ---------------- zero-init per launch --------------------------------------
__global__ void k_init(int n) {
    int tot = 2 * n + BB * 128 + 2 * BB * 64;
    for (int i = blockIdx.x * blockDim.x + threadIdx.x; i < tot;
         i += gridDim.x * blockDim.x) {
        if (i < n) g_deg[i] = 0;
        else if (i < 2 * n) g_cur[i - n] = 0;
        else {
            int j = i - 2 * n;
            if (j < BB * 128) g_qstar[j] = 0.f;
            else {
                j -= BB * 128;
                if (j < BB * 64) g_hs[j] = 0.f;
                else g_cs[j - BB * 64] = 0.f;
            }
        }
    }
}

// ---------------- Vs[k][h] = sum_c Wg[k, h*64+c] att_src[h,c] ---------------
__global__ void k_prevec(const float* __restrict__ Wg,
                         const float* __restrict__ att_src,
                         const float* __restrict__ att_dst) {
    int t = threadIdx.x;  // 512 threads
    int k = t >> 3, h = t & 7;
    float s = 0.f, d = 0.f;
    const float* wr = Wg + k * 512 + h * 64;
    const float* as = att_src + h * 64;
    const float* ad = att_dst + h * 64;
#pragma unroll 16
    for (int c = 0; c < 64; c++) {
        float w = wr[c];
        s += w * as[c];
        d += w * ad[c];
    }
    g_Vs[k * 8 + h] = s;
    g_Vd[k * 8 + h] = d;
}

// ---------------- h0 = relu(x @ W0 + b0); a_s/a_d = h0 @ [Vs|Vd] ------------
__global__ void k_h0attn(const float* __restrict__ x,
                         const float* __restrict__ W0,
                         const float* __restrict__ b0, int n) {
    __shared__ float Ws[25 * 64];
    __shared__ float xs[16][26];
    __shared__ float Vsm[64][17];
    __shared__ float h0s[16][65];
    int t = threadIdx.x;  // 256
    int n0 = blockIdx.x * 16;
    for (int idx = t; idx < 1600; idx += 256) Ws[idx] = W0[idx];
    for (int idx = t; idx < 400; idx += 256) {
        int r = idx / 25, k = idx % 25;
        int gr = n0 + r;
        xs[r][k] = (gr < n) ? x[gr * 25 + k] : 0.f;
    }
    for (int idx = t; idx < 1024; idx += 256) {
        int k = idx >> 4, o = idx & 15;
        Vsm[k][o] = (o < 8) ? g_Vs[k * 8 + o] : g_Vd[k * 8 + (o - 8)];
    }
    __syncthreads();
    int j = t & 63, rb = t >> 6;
#pragma unroll
    for (int i = 0; i < 4; i++) {
        int r = rb * 4 + i;
        float acc = b0[j];
#pragma unroll
        for (int k = 0; k < 25; k++) acc += xs[r][k] * Ws[k * 64 + j];
        float v = fmaxf(acc, 0.f);
        h0s[r][j] = v;
        int gr = n0 + r;
        if (gr < n) g_h0[gr * 64 + j] = v;
    }
    __syncthreads();
    int row = t >> 4, o = t & 15;
    float acc = 0.f;
#pragma unroll 16
    for (int k = 0; k < 64; k++) acc += h0s[row][k] * Vsm[k][o];
    int gr = n0 + row;
    if (gr < n) {
        if (o < 8) g_as[gr * 8 + o] = acc;
        else       g_ad[gr * 8 + (o - 8)] = acc;
    }
}

// ---------------- CSR build --------------------------------------------------
__global__ void k_count(int E, int n) {
    int tot = E + n;
    for (int i = blockIdx.x * blockDim.x + threadIdx.x; i < tot;
         i += gridDim.x * blockDim.x) {
        int d = (i < E) ? g_dst[i] : (i - E);  // self-loops appended
        atomicAdd(&g_deg[d], 1);
    }
}

__global__ void k_scan(int n) {
    __shared__ int sd[1024];
    __shared__ int carry;
    int t = threadIdx.x;
    if (t == 0) carry = 0;
    __syncthreads();
    for (int base = 0; base < n; base += 1024) {
        int v = (base + t < n) ? g_deg[base + t] : 0;
        sd[t] = v;
        __syncthreads();
        for (int o = 1; o < 1024; o <<= 1) {
            int xv = (t >= o) ? sd[t - o] : 0;
            __syncthreads();
            sd[t] += xv;
            __syncthreads();
        }
        int cprev = carry;
        if (base + t < n) g_off[base + t] = cprev + sd[t] - v;
        __syncthreads();
        if (t == 0) carry = cprev + sd[1023];
        __syncthreads();
    }
    if (t == 0) g_off[n] = carry;
}

__global__ void k_scatter(int E, int n) {
    int tot = E + n;
    for (int i = blockIdx.x * blockDim.x + threadIdx.x; i < tot;
         i += gridDim.x * blockDim.x) {
        int d = (i < E) ? g_dst[i] : (i - E);
        int s = (i < E) ? g_src[i] : (i - E);
        int pos = g_off[d] + atomicAdd(&g_cur[d], 1);
        g_csr[pos] = s;
    }
}

// ---------------- per-dst softmax + aggregate in h0-space -------------------
// aggpre[dst, h*64+k] = sum_e alpha[e,h] * h0[src_e, k]
__global__ void k_agg(int n) {
    int dst = blockIdx.x;
    int t = threadIdx.x;  // 128
    int lane = t & 31, wrp = t >> 5;
    __shared__ float s_m[8], s_inv[8];
    __shared__ float scratch[32];
    __shared__ int   s_srcb[16];
    __shared__ float s_al[16][8];
    __shared__ float s_h0[16][68];
    int start = g_off[dst], end = g_off[dst + 1];
    float ad[8];
#pragma unroll
    for (int h = 0; h < 8; h++) ad[h] = g_ad[dst * 8 + h];

    // pass 1: max per head
    float lm[8];
#pragma unroll
    for (int h = 0; h < 8; h++) lm[h] = -1e30f;
    for (int jj = start + t; jj < end; jj += 128) {
        int s = g_csr[jj];
        const float* ap = g_as + s * 8;
#pragma unroll
        for (int h = 0; h < 8; h++) {
            float e = ap[h] + ad[h];
            e = (e > 0.f) ? e : 0.2f * e;
            lm[h] = fmaxf(lm[h], e);
        }
    }
#pragma unroll
    for (int h = 0; h < 8; h++)
        for (int o = 16; o; o >>= 1)
            lm[h] = fmaxf(lm[h], __shfl_xor_sync(0xffffffffu, lm[h], o));
    if (lane == 0)
#pragma unroll
        for (int h = 0; h < 8; h++) scratch[wrp * 8 + h] = lm[h];
    __syncthreads();
    if (t < 8)
        s_m[t] = fmaxf(fmaxf(scratch[t], scratch[8 + t]),
                       fmaxf(scratch[16 + t], scratch[24 + t]));
    __syncthreads();
    float mh[8];
#pragma unroll
    for (int h = 0; h < 8; h++) mh[h] = s_m[h];

    // pass 2: sum of exp
    float ls[8];
#pragma unroll
    for (int h = 0; h < 8; h++) ls[h] = 0.f;
    for (int jj = start + t; jj < end; jj += 128) {
        int s = g_csr[jj];
        const float* ap = g_as + s * 8;
#pragma unroll
        for (int h = 0; h < 8; h++) {
            float e = ap[h] + ad[h];
            e = (e > 0.f) ? e : 0.2f * e;
            ls[h] += __expf(e - mh[h]);
        }
    }
#pragma unroll
    for (int h = 0; h < 8; h++)
        for (int o = 16; o; o >>= 1)
            ls[h] += __shfl_xor_sync(0xffffffffu, ls[h], o);
    if (lane == 0)
#pragma unroll
        for (int h = 0; h < 8; h++) scratch[wrp * 8 + h] = ls[h];
    __syncthreads();
    if (t < 8) {
        float sm = scratch[t] + scratch[8 + t] + scratch[16 + t] + scratch[24 + t];
        s_inv[t] = 1.f / sm;
    }
    __syncthreads();
    float inv[8];
#pragma unroll
    for (int h = 0; h < 8; h++) inv[h] = s_inv[h];

    // pass 3: weighted gather of h0 (256 B / edge), chunks of 16 edges
    int ht = t >> 4, c0 = (t & 15) * 4;
    float4 acc = make_float4(0.f, 0.f, 0.f, 0.f);
    for (int base = start; base < end; base += 16) {
        int cnt = min(16, end - base);
        __syncthreads();
        if (t < cnt) {
            int s = g_csr[base + t];
            s_srcb[t] = s;
            const float* ap = g_as + s * 8;
#pragma unroll
            for (int h = 0; h < 8; h++) {
                float e = ap[h] + ad[h];
                e = (e > 0.f) ? e : 0.2f * e;
                s_al[t][h] = __expf(e - mh[h]) * inv[h];
            }
        }
        __syncthreads();
        for (int idx = t; idx < cnt * 16; idx += 128) {
            int r = idx >> 4, c4 = idx & 15;
            ((float4*)s_h0[r])[c4] =
                ((const float4*)(g_h0 + (size_t)s_srcb[r] * 64))[c4];
        }
        __syncthreads();
#pragma unroll 4
        for (int j = 0; j < cnt; j++) {
            float al = s_al[j][ht];
            float4 v = *(const float4*)(&s_h0[j][c0]);
            acc.x += al * v.x;
            acc.y += al * v.y;
            acc.z += al * v.z;
            acc.w += al * v.w;
        }
    }
    *(float4*)(g_pre + (size_t)dst * 512 + t * 4) = acc;
}

// ---------------- fused: out = relu(relu(pre (x)_h Wg_h + bg) @ Wh + bh) ----
__global__ void k_fused(const float* __restrict__ Wg,
                        const float* __restrict__ bg,
                        const float* __restrict__ Wh,
                        const float* __restrict__ bh, int n) {
    __shared__ float Pb[64][68];   // P_h: [k][row]
    __shared__ float Wgb[64][68];  // Wg_h: [k][c]
    __shared__ float Whb[64][68];  // Wh_h: [c][c2]
    __shared__ float Tb[64][68];   // T_h: [c][row]
    int row0 = blockIdx.x * 64;
    int t = threadIdx.x;  // 256
    int tx = t & 15, ty = t >> 4;
    float acc[4][4];
#pragma unroll
    for (int i = 0; i < 4; i++)
#pragma unroll
        for (int j = 0; j < 4; j++) acc[i][j] = 0.f;

    for (int h = 0; h < 8; h++) {
        __syncthreads();
        for (int idx = t; idx < 4096; idx += 256) {
            int r = idx >> 6, k = idx & 63;
            int gr = row0 + r;
            Pb[k][r] = (gr < n) ? g_pre[(size_t)gr * 512 + h * 64 + k] : 0.f;
        }
        for (int idx = t; idx < 4096; idx += 256) {
            int k = idx >> 6, c = idx & 63;
            Wgb[k][c] = Wg[k * 512 + h * 64 + c];
            Whb[k][c] = Wh[(h * 64 + k) * 64 + c];
        }
        __syncthreads();
        float t4[4][4];
#pragma unroll
        for (int i = 0; i < 4; i++)
#pragma unroll
            for (int j = 0; j < 4; j++) t4[i][j] = 0.f;
#pragma unroll 8
        for (int k = 0; k < 64; k++) {
            float a0 = Pb[k][ty * 4 + 0], a1 = Pb[k][ty * 4 + 1];
            float a2 = Pb[k][ty * 4 + 2], a3 = Pb[k][ty * 4 + 3];
            float b0 = Wgb[k][tx * 4 + 0], b1 = Wgb[k][tx * 4 + 1];
            float b2 = Wgb[k][tx * 4 + 2], b3 = Wgb[k][tx * 4 + 3];
            t4[0][0] += a0 * b0; t4[0][1] += a0 * b1; t4[0][2] += a0 * b2; t4[0][3] += a0 * b3;
            t4[1][0] += a1 * b0; t4[1][1] += a1 * b1; t4[1][2] += a1 * b2; t4[1][3] += a1 * b3;
            t4[2][0] += a2 * b0; t4[2][1] += a2 * b1; t4[2][2] += a2 * b2; t4[2][3] += a2 * b3;
            t4[3][0] += a3 * b0; t4[3][1] += a3 * b1; t4[3][2] += a3 * b2; t4[3][3] += a3 * b3;
        }
#pragma unroll
        for (int j = 0; j < 4; j++) {
            float bgv = bg[h * 64 + tx * 4 + j];
#pragma unroll
            for (int i = 0; i < 4; i++)
                Tb[tx * 4 + j][ty * 4 + i] = fmaxf(t4[i][j] + bgv, 0.f);
        }
        __syncthreads();
#pragma unroll 8
        for (int k = 0; k < 64; k++) {
            float a0 = Tb[k][ty * 4 + 0], a1 = Tb[k][ty * 4 + 1];
            float a2 = Tb[k][ty * 4 + 2], a3 = Tb[k][ty * 4 + 3];
            float b0 = Whb[k][tx * 4 + 0], b1 = Whb[k][tx * 4 + 1];
            float b2 = Whb[k][tx * 4 + 2], b3 = Whb[k][tx * 4 + 3];
            acc[0][0] += a0 * b0; acc[0][1] += a0 * b1; acc[0][2] += a0 * b2; acc[0][3] += a0 * b3;
            acc[1][0] += a1 * b0; acc[1][1] += a1 * b1; acc[1][2] += a1 * b2; acc[1][3] += a1 * b3;
            acc[2][0] += a2 * b0; acc[2][1] += a2 * b1; acc[2][2] += a2 * b2; acc[2][3] += a2 * b3;
            acc[3][0] += a3 * b0; acc[3][1] += a3 * b1; acc[3][2] += a3 * b2; acc[3][3] += a3 * b3;
        }
    }
    float bh0 = bh[tx * 4 + 0], bh1 = bh[tx * 4 + 1];
    float bh2 = bh[tx * 4 + 2], bh3 = bh[tx * 4 + 3];
#pragma unroll
    for (int i = 0; i < 4; i++) {
        int gr = row0 + ty * 4 + i;
        if (gr < n) {
            float4 v;
            v.x = fmaxf(acc[i][0] + bh0, 0.f);
            v.y = fmaxf(acc[i][1] + bh1, 0.f);
            v.z = fmaxf(acc[i][2] + bh2, 0.f);
            v.w = fmaxf(acc[i][3] + bh3, 0.f);
            *(float4*)(g_outf + gr * 64 + tx * 4) = v;
        }
    }
}

// ---------------- segment boundaries for sorted batch -----------------------
__global__ void k_segstart(int n) {
    int b = threadIdx.x;
    if (b > BB) return;
    if (b == BB) { g_seg[BB] = n; return; }
    int lo = 0, hi = n;
    while (lo < hi) {
        int mid = (lo + hi) >> 1;
        if (g_batch[mid] < b) lo = mid + 1;
        else hi = mid;
    }
    g_seg[b] = lo;
}

// ---------------- LSTM cell (Set2Set) ---------------------------------------
__global__ void k_lstm(const float* __restrict__ W_ih,
                       const float* __restrict__ W_hh,
                       const float* __restrict__ b_ih,
                       const float* __restrict__ b_hh) {
    int b = blockIdx.x, j = threadIdx.x;  // 256 threads
    __shared__ float sq[128], sh[64], gg[256];
    if (j < 128) sq[j] = g_qstar[b * 128 + j];
    if (j < 64) sh[j] = g_hs[b * 64 + j];
    __syncthreads();
    float acc = b_ih[j] + b_hh[j];
    const float* wr = W_ih + j * 128;
#pragma unroll 8
    for (int k = 0; k < 128; k++) acc += sq[k] * wr[k];
    const float* wr2 = W_hh + j * 64;
#pragma unroll 8
    for (int k = 0; k < 64; k++) acc += sh[k] * wr2[k];
    gg[j] = acc;
    __syncthreads();
    if (j < 64) {
        float ig = 1.f / (1.f + __expf(-gg[j]));
        float fg = 1.f / (1.f + __expf(-gg[64 + j]));
        float gv = tanhf(gg[128 + j]);
        float og = 1.f / (1.f + __expf(-gg[192 + j]));
        float cn = fg * g_cs[b * 64 + j] + ig * gv;
        float hn = og * tanhf(cn);
        g_cs[b * 64 + j] = cn;
        g_hs[b * 64 + j] = hn;
    }
}

// ---------------- attention pooling (Set2Set) -------------------------------
__device__ __forceinline__ float blkmax128(float v, float* sb) {
    for (int o = 16; o; o >>= 1) v = fmaxf(v, __shfl_xor_sync(0xffffffffu, v, o));
    if ((threadIdx.x & 31) == 0) sb[threadIdx.x >> 5] = v;
    __syncthreads();
    v = fmaxf(fmaxf(sb[0], sb[1]), fmaxf(sb[2], sb[3]));
    __syncthreads();
    return v;
}
__device__ __forceinline__ float blksum128(float v, float* sb) {
    for (int o = 16; o; o >>= 1) v += __shfl_xor_sync(0xffffffffu, v, o);
    if ((threadIdx.x & 31) == 0) sb[threadIdx.x >> 5] = v;
    __syncthreads();
    v = sb[0] + sb[1] + sb[2] + sb[3];
    __syncthreads();
    return v;
}

__global__ void k_pool() {
    int b = blockIdx.x, t = threadIdx.x;  // 128
    __shared__ float q[64];
    __shared__ float sb[4];
    int s0 = g_seg[b], s1 = g_seg[b + 1];
    if (t < 64) q[t] = g_hs[b * 64 + t];
    __syncthreads();
    float mx = -1e30f;
    for (int i = s0 + t; i < s1; i += 128) {
        const float* row = g_outf + i * 64;
        float d = 0.f;
#pragma unroll
        for (int c = 0; c < 64; c += 4) {
            float4 v = *(const float4*)(row + c);
            d += v.x * q[c] + v.y * q[c + 1] + v.z * q[c + 2] + v.w * q[c + 3];
        }
        g_e2[i] = d;
        mx = fmaxf(mx, d);
    }
    mx = blkmax128(mx, sb);
    float sm = 0.f;
    for (int i = s0 + t; i < s1; i += 128) {
        float w = __expf(g_e2[i] - mx);
        g_e2[i] = w;
        sm += w;
    }
    sm = blksum128(sm, sb);
    float inv = (sm > 0.f) ? 1.f / sm : 0.f;
    if (t < 64) {
        float r = 0.f;
        for (int i = s0; i < s1; i++) r += g_e2[i] * g_outf[i * 64 + t];
        g_qstar[b * 128 + t] = q[t];
        g_qstar[b * 128 + 64 + t] = r * inv;
    }
}

// ---------------- final MLP: y = relu(q_star@W1+b1)@W2 + b2 -----------------
__global__ void k_final(const float* __restrict__ W1, const float* __restrict__ b1,
                        const float* __restrict__ W2, const float* __restrict__ b2,
                        float* __restrict__ y) {
    int b = blockIdx.x, j = threadIdx.x;  // 64 threads
    __shared__ float sq[128];
    __shared__ float sb[2];
    sq[j] = g_qstar[b * 128 + j];
    sq[64 + j] = g_qstar[b * 128 + 64 + j];
    __syncthreads();
    float acc = b1[j];
#pragma unroll 8
    for (int k = 0; k < 128; k++) acc += sq[k] * W1[k * 64 + j];
    float z = fmaxf(acc, 0.f) * W2[j];
    for (int o = 16; o; o >>= 1) z += __shfl_xor_sync(0xffffffffu, z, o);
    if ((j & 31) == 0) sb[j >> 5] = z;
    __syncthreads();
    if (j == 0) y[b] = sb[0] + sb[1] + b2[0];
}

// ---------------- launcher ---------------------------------------------------
extern "C" void kernel_launch(void* const* d_in, const int* in_sizes, int n_in,
                              void* d_out, int out_size) {
    const float* x      = (const float*)d_in[0];
    const void*  edge   = d_in[1];
    const void*  batch  = d_in[2];
    const float* W0     = (const float*)d_in[3];
    const float* b0     = (const float*)d_in[4];
    const float* Wg     = (const float*)d_in[5];
    const float* att_s  = (const float*)d_in[6];
    const float* att_d  = (const float*)d_in[7];
    const float* bg     = (const float*)d_in[8];
    const float* Wh     = (const float*)d_in[9];
    const float* bh     = (const float*)d_in[10];
    const float* W_ih   = (const float*)d_in[11];
    const float* W_hh   = (const float*)d_in[12];
    const float* b_ih   = (const float*)d_in[13];
    const float* b_hh   = (const float*)d_in[14];
    const float* W1     = (const float*)d_in[15];
    const float* b1     = (const float*)d_in[16];
    const float* W2     = (const float*)d_in[17];
    const float* b2     = (const float*)d_in[18];
    float* y = (float*)d_out;

    int n = in_sizes[0] / 25;
    int E = in_sizes[1] / 2;

    k_detect<<<1, 256>>>((const int*)edge);
    k_convert<<<512, 256>>>(edge, batch, E, n);
    k_init<<<256, 256>>>(n);
    k_prevec<<<1, 512>>>(Wg, att_s, att_d);
    k_h0attn<<<(n + 15) / 16, 256>>>(x, W0, b0, n);
    k_count<<<1024, 256>>>(E, n);
    k_scan<<<1, 1024>>>(n);
    k_scatter<<<1024, 256>>>(E, n);
    k_agg<<<n, 128>>>(n);
    k_fused<<<(n + 63) / 64, 256>>>(Wg, bg, Wh, bh, n);
    k_segstart<<<1, 256>>>(n);
    for (int it = 0; it < 3; it++) {
        k_lstm<<<BB, 256>>>(W_ih, W_hh, b_ih, b_hh);
        k_pool<<<BB, 128>>>();
    }
    k_final<<<BB, 64>>>(W1, b1, W2, b2, y);
}

// round 5
// speedup vs baseline: 2.1471x; 2.0933x over previous
#include <cuda_runtime.h>

#define NN 20000
#define EE 320000
#define ET (EE + NN)
#define BB 128

// ---------------- scratch (device globals; no runtime allocation) ----------
__device__ int   g_flag;
__device__ int   g_src[EE], g_dst[EE], g_batch[NN];
__device__ int   g_deg[NN], g_cur[NN], g_off[NN + 1];
__device__ int   g_csr[ET];
__device__ float g_h0[NN * 64];
__device__ float g_pre[(size_t)NN * 512];      // aggpre [N][h*64+k]
__device__ float g_as[NN * 8], g_ad[NN * 8];
__device__ float g_Vs[64 * 8], g_Vd[64 * 8];
__device__ float g_outf[NN * 64];
__device__ float g_e2[NN];
__device__ float g_hs[BB * 64], g_cs[BB * 64], g_qstar[BB * 128];
__device__ int   g_seg[BB + 1];

// ---------------- dtype detection (int64 vs int32 index buffers) -----------
__global__ void k_detect(const int* buf) {
    int t = threadIdx.x;
    int any = 0;
    for (int i = 2 * t + 1; i < 2048; i += 2 * 256) any |= (buf[i] != 0);
    __shared__ int s;
    if (t == 0) s = 0;
    __syncthreads();
    if (any) atomicOr(&s, 1);
    __syncthreads();
    if (t == 0) g_flag = s ? 0 : 1;  // 1 => int64
}

// ---------------- zero/seed-init per launch ---------------------------------
__global__ void k_init(int n) {
    int tot = 2 * n + BB * 128 + 2 * BB * 64;
    for (int i = blockIdx.x * blockDim.x + threadIdx.x; i < tot;
         i += gridDim.x * blockDim.x) {
        if (i < n) g_deg[i] = 1;            // self-loop pre-counted
        else if (i < 2 * n) g_cur[i - n] = 0;
        else {
            int j = i - 2 * n;
            if (j < BB * 128) g_qstar[j] = 0.f;
            else {
                j -= BB * 128;
                if (j < BB * 64) g_hs[j] = 0.f;
                else g_cs[j - BB * 64] = 0.f;
            }
        }
    }
}

// ---------------- convert indices + count degrees ---------------------------
__global__ void k_convert(const void* edge, const void* batch, int E, int n) {
    int is64 = g_flag;
    for (int i = blockIdx.x * blockDim.x + threadIdx.x; i < E;
         i += gridDim.x * blockDim.x) {
        int s, d;
        if (is64) {
            const long long* p = (const long long*)edge;
            s = (int)p[i];
            d = (int)p[(size_t)E + i];
        } else {
            const int* p = (const int*)edge;
            s = p[i];
            d = p[E + i];
        }
        g_src[i] = s;
        g_dst[i] = d;
        atomicAdd(&g_deg[d], 1);
        if (i < n) {
            g_batch[i] = is64 ? (int)((const long long*)batch)[i]
                              : ((const int*)batch)[i];
        }
    }
}

// ---------------- Vs[k][h] = sum_c Wg[k, h*64+c] att_src[h,c] ---------------
// grid 64 (one block per k-row), 64 threads (c); coalesced loads.
__global__ void k_prevec(const float* __restrict__ Wg,
                         const float* __restrict__ att_src,
                         const float* __restrict__ att_dst) {
    int k = blockIdx.x, c = threadIdx.x;
    int lane = c & 31, w = c >> 5;
    __shared__ float sS[2][8], sD[2][8];
    float ps[8], pd[8];
#pragma unroll
    for (int h = 0; h < 8; h++) {
        float wv = Wg[k * 512 + h * 64 + c];
        ps[h] = wv * att_src[h * 64 + c];
        pd[h] = wv * att_dst[h * 64 + c];
    }
#pragma unroll
    for (int h = 0; h < 8; h++) {
        for (int o = 16; o; o >>= 1) {
            ps[h] += __shfl_xor_sync(0xffffffffu, ps[h], o);
            pd[h] += __shfl_xor_sync(0xffffffffu, pd[h], o);
        }
    }
    if (lane == 0) {
#pragma unroll
        for (int h = 0; h < 8; h++) { sS[w][h] = ps[h]; sD[w][h] = pd[h]; }
    }
    __syncthreads();
    if (c < 8) g_Vs[k * 8 + c] = sS[0][c] + sS[1][c];
    else if (c < 16) g_Vd[k * 8 + (c - 8)] = sD[0][c - 8] + sD[1][c - 8];
}

// ---------------- h0 = relu(x @ W0 + b0); a_s/a_d = h0 @ [Vs|Vd] ------------
__global__ void k_h0attn(const float* __restrict__ x,
                         const float* __restrict__ W0,
                         const float* __restrict__ b0, int n) {
    __shared__ float Ws[25 * 64];
    __shared__ float xs[16][26];
    __shared__ float Vsm[64][17];
    __shared__ float h0s[16][65];
    int t = threadIdx.x;  // 256
    int n0 = blockIdx.x * 16;
    for (int idx = t; idx < 1600; idx += 256) Ws[idx] = W0[idx];
    for (int idx = t; idx < 400; idx += 256) {
        int r = idx / 25, k = idx % 25;
        int gr = n0 + r;
        xs[r][k] = (gr < n) ? x[gr * 25 + k] : 0.f;
    }
    for (int idx = t; idx < 1024; idx += 256) {
        int k = idx >> 4, o = idx & 15;
        Vsm[k][o] = (o < 8) ? g_Vs[k * 8 + o] : g_Vd[k * 8 + (o - 8)];
    }
    __syncthreads();
    int j = t & 63, rb = t >> 6;
#pragma unroll
    for (int i = 0; i < 4; i++) {
        int r = rb * 4 + i;
        float acc = b0[j];
#pragma unroll
        for (int k = 0; k < 25; k++) acc += xs[r][k] * Ws[k * 64 + j];
        float v = fmaxf(acc, 0.f);
        h0s[r][j] = v;
        int gr = n0 + r;
        if (gr < n) g_h0[gr * 64 + j] = v;
    }
    __syncthreads();
    int row = t >> 4, o = t & 15;
    float acc = 0.f;
#pragma unroll 16
    for (int k = 0; k < 64; k++) acc += h0s[row][k] * Vsm[k][o];
    int gr = n0 + row;
    if (gr < n) {
        if (o < 8) g_as[gr * 8 + o] = acc;
        else       g_ad[gr * 8 + (o - 8)] = acc;
    }
}

// ---------------- exclusive scan (single block, warp shuffles) --------------
__global__ void k_scan(int n) {
    __shared__ int warp_sums[32];
    __shared__ int carry_s;
    int t = threadIdx.x, lane = t & 31, wid = t >> 5;
    if (t == 0) carry_s = 0;
    __syncthreads();
    for (int base = 0; base < n; base += 1024) {
        int v = (base + t < n) ? g_deg[base + t] : 0;
        int xv = v;
#pragma unroll
        for (int o = 1; o < 32; o <<= 1) {
            int y = __shfl_up_sync(0xffffffffu, xv, o);
            if (lane >= o) xv += y;
        }
        if (lane == 31) warp_sums[wid] = xv;
        __syncthreads();
        if (wid == 0) {
            int s = warp_sums[lane];
#pragma unroll
            for (int o = 1; o < 32; o <<= 1) {
                int y = __shfl_up_sync(0xffffffffu, s, o);
                if (lane >= o) s += y;
            }
            warp_sums[lane] = s;
        }
        __syncthreads();
        int c0 = carry_s;
        int pre = c0 + (wid ? warp_sums[wid - 1] : 0);
        if (base + t < n) g_off[base + t] = pre + xv - v;
        int tot = warp_sums[31];
        __syncthreads();
        if (t == 0) carry_s = c0 + tot;
    }
    __syncthreads();
    if (t == 0) g_off[n] = carry_s;
}

__global__ void k_scatter(int E, int n) {
    int tot = E + n;
    for (int i = blockIdx.x * blockDim.x + threadIdx.x; i < tot;
         i += gridDim.x * blockDim.x) {
        int d = (i < E) ? g_dst[i] : (i - E);
        int s = (i < E) ? g_src[i] : (i - E);
        int pos = g_off[d] + atomicAdd(&g_cur[d], 1);
        g_csr[pos] = s;
    }
}

// ---------------- warp-per-dst softmax + aggregate in h0-space --------------
// aggpre[dst, h*64+k] = sum_e alpha[e,h] * h0[src_e, k]
__global__ void k_agg(int n) {
    int gw = (blockIdx.x * blockDim.x + threadIdx.x) >> 5;
    int lane = threadIdx.x & 31;
    if (gw >= n) return;
    int start = g_off[gw], end = g_off[gw + 1];
    float4 adA = *(const float4*)(g_ad + gw * 8);
    float4 adB = *(const float4*)(g_ad + gw * 8 + 4);
    float ad0 = adA.x, ad1 = adA.y, ad2 = adA.z, ad3 = adA.w;
    float ad4 = adB.x, ad5 = adB.y, ad6 = adB.z, ad7 = adB.w;

    float lm[8];
#pragma unroll
    for (int h = 0; h < 8; h++) lm[h] = -1e30f;
    // pass 1: max
    for (int j = start + lane; j < end; j += 32) {
        int s = g_csr[j];
        float4 aA = *(const float4*)(g_as + s * 8);
        float4 aB = *(const float4*)(g_as + s * 8 + 4);
        float e;
        e = aA.x + ad0; e = (e > 0.f) ? e : 0.2f * e; lm[0] = fmaxf(lm[0], e);
        e = aA.y + ad1; e = (e > 0.f) ? e : 0.2f * e; lm[1] = fmaxf(lm[1], e);
        e = aA.z + ad2; e = (e > 0.f) ? e : 0.2f * e; lm[2] = fmaxf(lm[2], e);
        e = aA.w + ad3; e = (e > 0.f) ? e : 0.2f * e; lm[3] = fmaxf(lm[3], e);
        e = aB.x + ad4; e = (e > 0.f) ? e : 0.2f * e; lm[4] = fmaxf(lm[4], e);
        e = aB.y + ad5; e = (e > 0.f) ? e : 0.2f * e; lm[5] = fmaxf(lm[5], e);
        e = aB.z + ad6; e = (e > 0.f) ? e : 0.2f * e; lm[6] = fmaxf(lm[6], e);
        e = aB.w + ad7; e = (e > 0.f) ? e : 0.2f * e; lm[7] = fmaxf(lm[7], e);
    }
#pragma unroll
    for (int h = 0; h < 8; h++)
        for (int o = 16; o; o >>= 1)
            lm[h] = fmaxf(lm[h], __shfl_xor_sync(0xffffffffu, lm[h], o));
    // pass 2: sum of exp
    float ls[8];
#pragma unroll
    for (int h = 0; h < 8; h++) ls[h] = 0.f;
    for (int j = start + lane; j < end; j += 32) {
        int s = g_csr[j];
        float4 aA = *(const float4*)(g_as + s * 8);
        float4 aB = *(const float4*)(g_as + s * 8 + 4);
        float e;
        e = aA.x + ad0; e = (e > 0.f) ? e : 0.2f * e; ls[0] += __expf(e - lm[0]);
        e = aA.y + ad1; e = (e > 0.f) ? e : 0.2f * e; ls[1] += __expf(e - lm[1]);
        e = aA.z + ad2; e = (e > 0.f) ? e : 0.2f * e; ls[2] += __expf(e - lm[2]);
        e = aA.w + ad3; e = (e > 0.f) ? e : 0.2f * e; ls[3] += __expf(e - lm[3]);
        e = aB.x + ad4; e = (e > 0.f) ? e : 0.2f * e; ls[4] += __expf(e - lm[4]);
        e = aB.y + ad5; e = (e > 0.f) ? e : 0.2f * e; ls[5] += __expf(e - lm[5]);
        e = aB.z + ad6; e = (e > 0.f) ? e : 0.2f * e; ls[6] += __expf(e - lm[6]);
        e = aB.w + ad7; e = (e > 0.f) ? e : 0.2f * e; ls[7] += __expf(e - lm[7]);
    }
#pragma unroll
    for (int h = 0; h < 8; h++)
        for (int o = 16; o; o >>= 1)
            ls[h] += __shfl_xor_sync(0xffffffffu, ls[h], o);
    float inv[8];
#pragma unroll
    for (int h = 0; h < 8; h++) inv[h] = 1.f / ls[h];

    // scalars for lane<8 alpha computation (dynamic lane index -> select chain)
    float advl = (lane == 0) ? ad0 : (lane == 1) ? ad1 : (lane == 2) ? ad2 :
                 (lane == 3) ? ad3 : (lane == 4) ? ad4 : (lane == 5) ? ad5 :
                 (lane == 6) ? ad6 : ad7;
    float lml  = (lane == 0) ? lm[0] : (lane == 1) ? lm[1] : (lane == 2) ? lm[2] :
                 (lane == 3) ? lm[3] : (lane == 4) ? lm[4] : (lane == 5) ? lm[5] :
                 (lane == 6) ? lm[6] : lm[7];
    float invl = (lane == 0) ? inv[0] : (lane == 1) ? inv[1] : (lane == 2) ? inv[2] :
                 (lane == 3) ? inv[3] : (lane == 4) ? inv[4] : (lane == 5) ? inv[5] :
                 (lane == 6) ? inv[6] : inv[7];

    // pass 3: one edge at a time across the warp
    float2 acc[8];
#pragma unroll
    for (int h = 0; h < 8; h++) acc[h] = make_float2(0.f, 0.f);
    for (int j = start; j < end; j++) {
        int s = g_csr[j];
        float alv = 0.f;
        if (lane < 8) {
            float a = g_as[s * 8 + lane];
            float e = a + advl;
            e = (e > 0.f) ? e : 0.2f * e;
            alv = __expf(e - lml) * invl;
        }
        float2 v = *(const float2*)(g_h0 + (size_t)s * 64 + lane * 2);
#pragma unroll
        for (int h = 0; h < 8; h++) {
            float a = __shfl_sync(0xffffffffu, alv, h);
            acc[h].x += a * v.x;
            acc[h].y += a * v.y;
        }
    }
#pragma unroll
    for (int h = 0; h < 8; h++)
        *(float2*)(g_pre + (size_t)gw * 512 + h * 64 + lane * 2) = acc[h];
}

// ---------------- fused: out = relu(relu(pre (x)_h Wg_h + bg) @ Wh + bh) ----
__global__ void k_fused(const float* __restrict__ Wg,
                        const float* __restrict__ bg,
                        const float* __restrict__ Wh,
                        const float* __restrict__ bh, int n) {
    __shared__ float Pb[64][68];   // P_h: [k][row]
    __shared__ float Wgb[64][68];  // Wg_h: [k][c]
    __shared__ float Whb[64][68];  // Wh_h: [c][c2]
    __shared__ float Tb[64][68];   // T_h: [c][row]
    int row0 = blockIdx.x * 64;
    int t = threadIdx.x;  // 256
    int tx = t & 15, ty = t >> 4;
    float acc[4][4];
#pragma unroll
    for (int i = 0; i < 4; i++)
#pragma unroll
        for (int j = 0; j < 4; j++) acc[i][j] = 0.f;

    for (int h = 0; h < 8; h++) {
        __syncthreads();
        for (int idx = t; idx < 4096; idx += 256) {
            int r = idx >> 6, k = idx & 63;
            int gr = row0 + r;
            Pb[k][r] = (gr < n) ? g_pre[(size_t)gr * 512 + h * 64 + k] : 0.f;
        }
        for (int idx = t; idx < 4096; idx += 256) {
            int k = idx >> 6, c = idx & 63;
            Wgb[k][c] = Wg[k * 512 + h * 64 + c];
            Whb[k][c] = Wh[(h * 64 + k) * 64 + c];
        }
        __syncthreads();
        float t4[4][4];
#pragma unroll
        for (int i = 0; i < 4; i++)
#pragma unroll
            for (int j = 0; j < 4; j++) t4[i][j] = 0.f;
#pragma unroll 8
        for (int k = 0; k < 64; k++) {
            float a0 = Pb[k][ty * 4 + 0], a1 = Pb[k][ty * 4 + 1];
            float a2 = Pb[k][ty * 4 + 2], a3 = Pb[k][ty * 4 + 3];
            float b0 = Wgb[k][tx * 4 + 0], b1 = Wgb[k][tx * 4 + 1];
            float b2 = Wgb[k][tx * 4 + 2], b3 = Wgb[k][tx * 4 + 3];
            t4[0][0] += a0 * b0; t4[0][1] += a0 * b1; t4[0][2] += a0 * b2; t4[0][3] += a0 * b3;
            t4[1][0] += a1 * b0; t4[1][1] += a1 * b1; t4[1][2] += a1 * b2; t4[1][3] += a1 * b3;
            t4[2][0] += a2 * b0; t4[2][1] += a2 * b1; t4[2][2] += a2 * b2; t4[2][3] += a2 * b3;
            t4[3][0] += a3 * b0; t4[3][1] += a3 * b1; t4[3][2] += a3 * b2; t4[3][3] += a3 * b3;
        }
#pragma unroll
        for (int j = 0; j < 4; j++) {
            float bgv = bg[h * 64 + tx * 4 + j];
#pragma unroll
            for (int i = 0; i < 4; i++)
                Tb[tx * 4 + j][ty * 4 + i] = fmaxf(t4[i][j] + bgv, 0.f);
        }
        __syncthreads();
#pragma unroll 8
        for (int k = 0; k < 64; k++) {
            float a0 = Tb[k][ty * 4 + 0], a1 = Tb[k][ty * 4 + 1];
            float a2 = Tb[k][ty * 4 + 2], a3 = Tb[k][ty * 4 + 3];
            float b0 = Whb[k][tx * 4 + 0], b1 = Whb[k][tx * 4 + 1];
            float b2 = Whb[k][tx * 4 + 2], b3 = Whb[k][tx * 4 + 3];
            acc[0][0] += a0 * b0; acc[0][1] += a0 * b1; acc[0][2] += a0 * b2; acc[0][3] += a0 * b3;
            acc[1][0] += a1 * b0; acc[1][1] += a1 * b1; acc[1][2] += a1 * b2; acc[1][3] += a1 * b3;
            acc[2][0] += a2 * b0; acc[2][1] += a2 * b1; acc[2][2] += a2 * b2; acc[2][3] += a2 * b3;
            acc[3][0] += a3 * b0; acc[3][1] += a3 * b1; acc[3][2] += a3 * b2; acc[3][3] += a3 * b3;
        }
    }
    float bh0 = bh[tx * 4 + 0], bh1 = bh[tx * 4 + 1];
    float bh2 = bh[tx * 4 + 2], bh3 = bh[tx * 4 + 3];
#pragma unroll
    for (int i = 0; i < 4; i++) {
        int gr = row0 + ty * 4 + i;
        if (gr < n) {
            float4 v;
            v.x = fmaxf(acc[i][0] + bh0, 0.f);
            v.y = fmaxf(acc[i][1] + bh1, 0.f);
            v.z = fmaxf(acc[i][2] + bh2, 0.f);
            v.w = fmaxf(acc[i][3] + bh3, 0.f);
            *(float4*)(g_outf + gr * 64 + tx * 4) = v;
        }
    }
}

// ---------------- segment boundaries for sorted batch -----------------------
__global__ void k_segstart(int n) {
    int b = threadIdx.x;
    if (b > BB) return;
    if (b == BB) { g_seg[BB] = n; return; }
    int lo = 0, hi = n;
    while (lo < hi) {
        int mid = (lo + hi) >> 1;
        if (g_batch[mid] < b) lo = mid + 1;
        else hi = mid;
    }
    g_seg[b] = lo;
}

// ---------------- fused Set2Set step: LSTM + attention pool (+final) --------
__global__ void k_s2s(const float* __restrict__ W_ih,
                      const float* __restrict__ W_hh,
                      const float* __restrict__ b_ih,
                      const float* __restrict__ b_hh,
                      const float* __restrict__ W1, const float* __restrict__ b1,
                      const float* __restrict__ W2, const float* __restrict__ b2,
                      float* __restrict__ y, int do_final) {
    int b = blockIdx.x, t = threadIdx.x;  // 256 threads
    int lane = t & 31, wid = t >> 5;
    __shared__ float sq[128], shh[64], gg[256], q[64], sb[8];
    __shared__ float rr[4][64];
    __shared__ float qs2[128];
    if (t < 128) sq[t] = g_qstar[b * 128 + t];
    if (t < 64) shh[t] = g_hs[b * 64 + t];
    __syncthreads();
    // LSTM gates
    {
        float acc = b_ih[t] + b_hh[t];
        const float* wr = W_ih + t * 128;
#pragma unroll 8
        for (int k = 0; k < 128; k++) acc += sq[k] * wr[k];
        const float* wr2 = W_hh + t * 64;
#pragma unroll 8
        for (int k = 0; k < 64; k++) acc += shh[k] * wr2[k];
        gg[t] = acc;
    }
    __syncthreads();
    if (t < 64) {
        float ig = 1.f / (1.f + __expf(-gg[t]));
        float fg = 1.f / (1.f + __expf(-gg[64 + t]));
        float gv = tanhf(gg[128 + t]);
        float og = 1.f / (1.f + __expf(-gg[192 + t]));
        float cn = fg * g_cs[b * 64 + t] + ig * gv;
        float hn = og * tanhf(cn);
        g_cs[b * 64 + t] = cn;
        g_hs[b * 64 + t] = hn;
        q[t] = hn;
    }
    __syncthreads();
    int s0 = g_seg[b], s1 = g_seg[b + 1];
    // phase A: scores + max
    float mx = -1e30f;
    for (int i = s0 + t; i < s1; i += 256) {
        const float* row = g_outf + i * 64;
        float d = 0.f;
#pragma unroll
        for (int c = 0; c < 64; c += 4) {
            float4 v = *(const float4*)(row + c);
            d += v.x * q[c] + v.y * q[c + 1] + v.z * q[c + 2] + v.w * q[c + 3];
        }
        g_e2[i] = d;
        mx = fmaxf(mx, d);
    }
    for (int o = 16; o; o >>= 1) mx = fmaxf(mx, __shfl_xor_sync(0xffffffffu, mx, o));
    if (lane == 0) sb[wid] = mx;
    __syncthreads();
    mx = fmaxf(fmaxf(fmaxf(sb[0], sb[1]), fmaxf(sb[2], sb[3])),
               fmaxf(fmaxf(sb[4], sb[5]), fmaxf(sb[6], sb[7])));
    __syncthreads();
    // phase B: exp + sum
    float sm = 0.f;
    for (int i = s0 + t; i < s1; i += 256) {
        float w = __expf(g_e2[i] - mx);
        g_e2[i] = w;
        sm += w;
    }
    for (int o = 16; o; o >>= 1) sm += __shfl_xor_sync(0xffffffffu, sm, o);
    if (lane == 0) sb[wid] = sm;
    __syncthreads();
    sm = sb[0] + sb[1] + sb[2] + sb[3] + sb[4] + sb[5] + sb[6] + sb[7];
    float inv = (sm > 0.f) ? 1.f / sm : 0.f;
    __syncthreads();
    // phase C: weighted read-out, 4-way row split
    {
        int grp = t >> 6, ch = t & 63;
        float r = 0.f;
        for (int i = s0 + grp; i < s1; i += 4) r += g_e2[i] * g_outf[i * 64 + ch];
        rr[grp][ch] = r;
    }
    __syncthreads();
    if (t < 64) {
        float rt = (rr[0][t] + rr[1][t] + rr[2][t] + rr[3][t]) * inv;
        g_qstar[b * 128 + t] = q[t];
        g_qstar[b * 128 + 64 + t] = rt;
        qs2[t] = q[t];
        qs2[64 + t] = rt;
    }
    if (do_final) {
        __syncthreads();
        if (t < 64) {
            float a = b1[t];
#pragma unroll 8
            for (int k = 0; k < 128; k++) a += qs2[k] * W1[k * 64 + t];
            float z = fmaxf(a, 0.f) * W2[t];
            for (int o = 16; o; o >>= 1) z += __shfl_xor_sync(0xffffffffu, z, o);
            if (lane == 0) sb[wid] = z;
        }
        __syncthreads();
        if (t == 0) y[b] = sb[0] + sb[1] + b2[0];
    }
}

// ---------------- launcher ---------------------------------------------------
extern "C" void kernel_launch(void* const* d_in, const int* in_sizes, int n_in,
                              void* d_out, int out_size) {
    const float* x      = (const float*)d_in[0];
    const void*  edge   = d_in[1];
    const void*  batch  = d_in[2];
    const float* W0     = (const float*)d_in[3];
    const float* b0     = (const float*)d_in[4];
    const float* Wg     = (const float*)d_in[5];
    const float* att_s  = (const float*)d_in[6];
    const float* att_d  = (const float*)d_in[7];
    const float* bg     = (const float*)d_in[8];
    const float* Wh     = (const float*)d_in[9];
    const float* bh     = (const float*)d_in[10];
    const float* W_ih   = (const float*)d_in[11];
    const float* W_hh   = (const float*)d_in[12];
    const float* b_ih   = (const float*)d_in[13];
    const float* b_hh   = (const float*)d_in[14];
    const float* W1     = (const float*)d_in[15];
    const float* b1     = (const float*)d_in[16];
    const float* W2     = (const float*)d_in[17];
    const float* b2     = (const float*)d_in[18];
    float* y = (float*)d_out;

    int n = in_sizes[0] / 25;
    int E = in_sizes[1] / 2;

    k_detect<<<1, 256>>>((const int*)edge);
    k_init<<<256, 256>>>(n);
    k_convert<<<512, 256>>>(edge, batch, E, n);
    k_prevec<<<64, 64>>>(Wg, att_s, att_d);
    k_h0attn<<<(n + 15) / 16, 256>>>(x, W0, b0, n);
    k_scan<<<1, 1024>>>(n);
    k_scatter<<<1024, 256>>>(E, n);
    k_segstart<<<1, 256>>>(n);
    k_agg<<<(n + 7) / 8, 256>>>(n);
    k_fused<<<(n + 63) / 64, 256>>>(Wg, bg, Wh, bh, n);
    for (int it = 0; it < 3; it++) {
        k_s2s<<<BB, 256>>>(W_ih, W_hh, b_ih, b_hh, W1, b1, W2, b2, y,
                           it == 2 ? 1 : 0);
    }
}